// round 7
// baseline (speedup 1.0000x reference)
#include <cuda_runtime.h>
#include <stdint.h>

// EdgeFeaturizer R7: persistent blocks, static row stride, 4-slot cp.async.bulk
// ring with fresh mbarrier lifecycle (inval+init) per refill. Parity always 0.

#define N_ATOMS   8192
#define KNBR      12
#define NBINS     50
#define CAP       192
#define THREADS   256
#define T0        0.0035f
#define CHUNKS    4
#define CHUNK_F   2048          // floats per chunk (8 KB)
#define CHUNK_V   512           // float4 per chunk
#define GRID      888           // 148 SMs * 6 blocks resident

__device__ __forceinline__ unsigned smem_u32(const void* p) {
    return (unsigned)__cvta_generic_to_shared(p);
}

__device__ __forceinline__ void mbar_wait0(unsigned mb) {
    unsigned done;
    asm volatile(
        "{\n\t.reg .pred p;\n\t"
        "mbarrier.try_wait.parity.acquire.cta.shared::cta.b64 p, [%1], 0;\n\t"
        "selp.b32 %0, 1, 0, p;\n\t}"
        : "=r"(done) : "r"(mb) : "memory");
    if (!done) {
        asm volatile(
            "{\n\t.reg .pred P1;\n\t"
            "WL_%=:\n\t"
            "mbarrier.try_wait.parity.acquire.cta.shared::cta.b64 P1, [%0], 0, 0x989680;\n\t"
            "@P1 bra.uni WD_%=;\n\t"
            "bra.uni WL_%=;\n\t"
            "WD_%=:\n\t}"
            :: "r"(mb) : "memory");
    }
}

__device__ __forceinline__ void arm_issue(const float* __restrict__ dm,
                                          float* slot, unsigned mb,
                                          int row, int c) {
    const char* src = (const char*)(dm + (size_t)row * N_ATOMS + (size_t)c * CHUNK_F);
    unsigned dst = smem_u32(slot);
    asm volatile("mbarrier.arrive.expect_tx.shared.b64 _, [%0], %1;"
                 :: "r"(mb), "r"(CHUNK_F * 4) : "memory");
    asm volatile(
        "cp.async.bulk.shared::cta.global.mbarrier::complete_tx::bytes "
        "[%0], [%1], %2, [%3];"
        :: "r"(dst), "l"(src), "r"(CHUNK_F * 4), "r"(mb) : "memory");
}

__global__ __launch_bounds__(THREADS, 6)
void edge_featurizer_kernel(const float* __restrict__ dm, float* __restrict__ out)
{
    __shared__ __align__(128) float ring[CHUNKS][CHUNK_F];   // 32 KB
    __shared__ unsigned long long cand[CAP];
    __shared__ int   s_cnt;
    __shared__ float s_tc[NBINS];
    __shared__ float s_d[KNBR];
    __shared__ int   s_i[KNBR];
    __shared__ float s_feat[KNBR * NBINS];
    __shared__ __align__(8) unsigned long long s_mbar[CHUNKS];

    const int tid = threadIdx.x;

    if (tid < NBINS) {
        float c = (float)tid * (1.0f / 49.0f);
        s_tc[tid] = __expf(-12.5f * c * c);
    }
    if (tid == 0) {
        s_cnt = 0;
        #pragma unroll
        for (int c = 0; c < CHUNKS; c++)
            asm volatile("mbarrier.init.shared.b64 [%0], 1;"
                         :: "r"(smem_u32(&s_mbar[c])) : "memory");
    }
    __syncthreads();

    int r_cur = blockIdx.x;
    if (tid == 0) {
        #pragma unroll
        for (int c = 0; c < CHUNKS; c++)
            arm_issue(dm, ring[c], smem_u32(&s_mbar[c]), r_cur, c);
    }

    for (;;) {
        const int r_next = r_cur + GRID;   // uniform, locally computed

        // ---- scan 4 chunks; re-init + refill each slot for the next row ----
        #pragma unroll
        for (int c = 0; c < CHUNKS; c++) {
            mbar_wait0(smem_u32(&s_mbar[c]));
            const float4* s4 = reinterpret_cast<const float4*>(ring[c]);
            const int i0 = tid;
            const int i1 = tid + THREADS;
            float4 v0 = s4[i0];
            float4 v1 = s4[i1];
            float m0 = fminf(fminf(v0.x, v0.y), fminf(v0.z, v0.w));
            float m1 = fminf(fminf(v1.x, v1.y), fminf(v1.z, v1.w));
            if (fminf(m0, m1) < T0) {                 // rare per-thread body
                #pragma unroll
                for (int j = 0; j < 2; j++) {
                    float4 v = (j == 0) ? v0 : v1;
                    int   li = (j == 0) ? i0 : i1;
                    int h = (v.x < T0) + (v.y < T0) + (v.z < T0) + (v.w < T0);
                    if (h) {
                        int p = atomicAdd(&s_cnt, h);
                        unsigned base = 4u * (unsigned)(c * CHUNK_V + li);
                        if (v.x < T0 && p < CAP)
                            cand[p++] = (((unsigned long long)__float_as_uint(v.x)) << 32) | (base + 0u);
                        if (v.y < T0 && p < CAP)
                            cand[p++] = (((unsigned long long)__float_as_uint(v.y)) << 32) | (base + 1u);
                        if (v.z < T0 && p < CAP)
                            cand[p++] = (((unsigned long long)__float_as_uint(v.z)) << 32) | (base + 2u);
                        if (v.w < T0 && p < CAP)
                            cand[p++] = (((unsigned long long)__float_as_uint(v.w)) << 32) | (base + 3u);
                    }
                }
            }
            __syncthreads();             // all consumed slot c; phase complete
            if (tid == 0 && r_next < N_ATOMS) {
                unsigned mb = smem_u32(&s_mbar[c]);
                asm volatile("mbarrier.inval.shared.b64 [%0];" :: "r"(mb) : "memory");
                asm volatile("mbarrier.init.shared.b64 [%0], 1;" :: "r"(mb) : "memory");
                arm_issue(dm, ring[c], mb, r_next, c);
            }
        }

        // ---- exact fallback (rare): rescan this row from GLOBAL ----
        int cc = s_cnt;
        if (cc < KNBR || cc > CAP) {
            const float4* g4 = reinterpret_cast<const float4*>(dm + (size_t)r_cur * N_ATOMS);
            float t = T0;
            while (cc < KNBR || cc > CAP) {
                t = (cc < KNBR) ? t * 8.0f : t * 0.25f;
                __syncthreads();
                if (tid == 0) s_cnt = 0;
                __syncthreads();
                for (int i = tid; i < N_ATOMS / 4; i += THREADS) {
                    float4 v = __ldg(g4 + i);
                    if (fminf(fminf(v.x, v.y), fminf(v.z, v.w)) < t) {
                        int h = (v.x < t) + (v.y < t) + (v.z < t) + (v.w < t);
                        int p = atomicAdd(&s_cnt, h);
                        unsigned base = 4u * (unsigned)i;
                        if (v.x < t && p < CAP)
                            cand[p++] = (((unsigned long long)__float_as_uint(v.x)) << 32) | (base + 0u);
                        if (v.y < t && p < CAP)
                            cand[p++] = (((unsigned long long)__float_as_uint(v.y)) << 32) | (base + 1u);
                        if (v.z < t && p < CAP)
                            cand[p++] = (((unsigned long long)__float_as_uint(v.z)) << 32) | (base + 2u);
                        if (v.w < t && p < CAP)
                            cand[p++] = (((unsigned long long)__float_as_uint(v.w)) << 32) | (base + 3u);
                    }
                }
                __syncthreads();
                cc = s_cnt;
                __syncthreads();
            }
        }

        // ---- parallel rank selection (keys unique -> ranks distinct) ----
        if (tid < cc) {
            unsigned long long mine = cand[tid];
            int rank = 0;
            int j = 0;
            for (; j + 4 <= cc; j += 4) {
                rank += (cand[j + 0] < mine);
                rank += (cand[j + 1] < mine);
                rank += (cand[j + 2] < mine);
                rank += (cand[j + 3] < mine);
            }
            for (; j < cc; j++) rank += (cand[j] < mine);
            if (rank < KNBR) {
                s_d[rank] = __uint_as_float((unsigned)(mine >> 32));
                s_i[rank] = (int)(mine & 0xffffffffu);
            }
        }
        if (tid == 0) s_cnt = 0;
        __syncthreads();

        // ---- features: geometric recurrence (2 MUFU per edge) ----
        if (tid < KNBR) {
            float d  = s_d[tid];
            float e0 = __expf(-12.5f * d * d);
            float g  = __expf((25.0f / 49.0f) * d);
            float p  = e0;
            #pragma unroll
            for (int j = 0; j < NBINS; j++) {
                s_feat[tid * NBINS + j] = p * s_tc[j];
                p *= g;
            }
            size_t eo = (size_t)r_cur * (2 * KNBR) + 2 * tid;
            out[eo]     = (float)r_cur;
            out[eo + 1] = (float)s_i[tid];
        }
        __syncthreads();

        // ---- coalesced feature writeback ----
        float* __restrict__ outF = out + (size_t)N_ATOMS * KNBR * 2
                                       + (size_t)r_cur * (KNBR * NBINS);
        #pragma unroll
        for (int i = tid; i < KNBR * NBINS; i += THREADS)
            outF[i] = s_feat[i];

        r_cur = r_next;
        if (r_cur >= N_ATOMS) break;       // uniform; matches refill guard
    }
}

extern "C" void kernel_launch(void* const* d_in, const int* in_sizes, int n_in,
                              void* d_out, int out_size)
{
    (void)in_sizes; (void)n_in; (void)out_size;
    const float* dm = (const float*)d_in[0];
    float* out = (float*)d_out;
    edge_featurizer_kernel<<<GRID, THREADS>>>(dm, out);
}

// round 8
// speedup vs baseline: 1.1491x; 1.1491x over previous
#include <cuda_runtime.h>
#include <stdint.h>

// EdgeFeaturizer R8: persistent blocks, 2x32KB double-buffered rows (cp.async.bulk),
// occupancy 3, static row stride. Tail and fill latency hidden under delivery.

#define N_ATOMS   8192
#define KNBR      12
#define NBINS     50
#define CAP       192
#define THREADS   256
#define T0        0.0035f
#define GRID      444           // 148 SMs * 3 blocks resident
#define ROW_F     N_ATOMS       // floats per row
#define ROW_B     (N_ATOMS * 4) // 32 KB

struct Smem {
    float buf[2][ROW_F];                        // 64 KB
    unsigned long long cand[CAP];
    unsigned long long mbar[2];
    float tc[NBINS];
    float d[KNBR];
    int   idx[KNBR];
    float feat[KNBR * NBINS];
    int   cnt;
};

__device__ __forceinline__ unsigned smem_u32(const void* p) {
    return (unsigned)__cvta_generic_to_shared(p);
}

__device__ __forceinline__ void mbar_wait0(unsigned mb) {
    unsigned done;
    asm volatile(
        "{\n\t.reg .pred p;\n\t"
        "mbarrier.try_wait.parity.acquire.cta.shared::cta.b64 p, [%1], 0;\n\t"
        "selp.b32 %0, 1, 0, p;\n\t}"
        : "=r"(done) : "r"(mb) : "memory");
    if (!done) {
        asm volatile(
            "{\n\t.reg .pred P1;\n\t"
            "WL_%=:\n\t"
            "mbarrier.try_wait.parity.acquire.cta.shared::cta.b64 P1, [%0], 0, 0x989680;\n\t"
            "@P1 bra.uni WD_%=;\n\t"
            "bra.uni WL_%=;\n\t"
            "WD_%=:\n\t}"
            :: "r"(mb) : "memory");
    }
}

// Fresh single-phase mbar lifecycle + one 32 KB bulk copy (R7-validated pattern).
__device__ __forceinline__ void arm_row(const float* __restrict__ dm,
                                        float* buf, unsigned mb, int row) {
    asm volatile("mbarrier.inval.shared.b64 [%0];" :: "r"(mb) : "memory");
    asm volatile("mbarrier.init.shared.b64 [%0], 1;" :: "r"(mb) : "memory");
    asm volatile("mbarrier.arrive.expect_tx.shared.b64 _, [%0], %1;"
                 :: "r"(mb), "r"(ROW_B) : "memory");
    asm volatile(
        "cp.async.bulk.shared::cta.global.mbarrier::complete_tx::bytes "
        "[%0], [%1], %2, [%3];"
        :: "r"(smem_u32(buf)), "l"((const char*)(dm + (size_t)row * ROW_F)),
           "r"(ROW_B), "r"(mb) : "memory");
}

__global__ __launch_bounds__(THREADS)
void edge_featurizer_kernel(const float* __restrict__ dm, float* __restrict__ out)
{
    extern __shared__ __align__(128) char smem_raw[];
    Smem* S = reinterpret_cast<Smem*>(smem_raw);

    const int tid = threadIdx.x;
    const int b   = blockIdx.x;

    if (tid < NBINS) {
        float c = (float)tid * (1.0f / 49.0f);
        S->tc[tid] = __expf(-12.5f * c * c);
    }
    if (tid == 0) {
        S->cnt = 0;
        asm volatile("mbarrier.init.shared.b64 [%0], 1;"
                     :: "r"(smem_u32(&S->mbar[0])) : "memory");
        asm volatile("mbarrier.init.shared.b64 [%0], 1;"
                     :: "r"(smem_u32(&S->mbar[1])) : "memory");
    }
    __syncthreads();

    if (tid == 0) {
        // prologue: arm both buffers (every block has >= 18 rows)
        asm volatile("mbarrier.arrive.expect_tx.shared.b64 _, [%0], %1;"
                     :: "r"(smem_u32(&S->mbar[0])), "r"(ROW_B) : "memory");
        asm volatile(
            "cp.async.bulk.shared::cta.global.mbarrier::complete_tx::bytes "
            "[%0], [%1], %2, [%3];"
            :: "r"(smem_u32(S->buf[0])), "l"((const char*)(dm + (size_t)b * ROW_F)),
               "r"(ROW_B), "r"(smem_u32(&S->mbar[0])) : "memory");
        asm volatile("mbarrier.arrive.expect_tx.shared.b64 _, [%0], %1;"
                     :: "r"(smem_u32(&S->mbar[1])), "r"(ROW_B) : "memory");
        asm volatile(
            "cp.async.bulk.shared::cta.global.mbarrier::complete_tx::bytes "
            "[%0], [%1], %2, [%3];"
            :: "r"(smem_u32(S->buf[1])), "l"((const char*)(dm + (size_t)(b + GRID) * ROW_F)),
               "r"(ROW_B), "r"(smem_u32(&S->mbar[1])) : "memory");
    }

    int k = 0;
    for (int r = b; r < N_ATOMS; r += GRID, k++) {
        const int p = k & 1;
        mbar_wait0(smem_u32(&S->mbar[p]));

        // ---- scan 32 KB from SMEM: 8 float4 per thread ----
        const float4* s4 = reinterpret_cast<const float4*>(S->buf[p]);
        #pragma unroll
        for (int g = 0; g < 2; g++) {
            const int i0 = tid + (g * 4 + 0) * THREADS;
            const int i1 = tid + (g * 4 + 1) * THREADS;
            const int i2 = tid + (g * 4 + 2) * THREADS;
            const int i3 = tid + (g * 4 + 3) * THREADS;
            float4 v0 = s4[i0];
            float4 v1 = s4[i1];
            float4 v2 = s4[i2];
            float4 v3 = s4[i3];
            float m0 = fminf(fminf(v0.x, v0.y), fminf(v0.z, v0.w));
            float m1 = fminf(fminf(v1.x, v1.y), fminf(v1.z, v1.w));
            float m2 = fminf(fminf(v2.x, v2.y), fminf(v2.z, v2.w));
            float m3 = fminf(fminf(v3.x, v3.y), fminf(v3.z, v3.w));
            if (fminf(fminf(m0, m1), fminf(m2, m3)) < T0) {   // rare body
                #pragma unroll
                for (int j = 0; j < 4; j++) {
                    float4 v = (j == 0) ? v0 : (j == 1) ? v1 : (j == 2) ? v2 : v3;
                    int    i = (j == 0) ? i0 : (j == 1) ? i1 : (j == 2) ? i2 : i3;
                    int h = (v.x < T0) + (v.y < T0) + (v.z < T0) + (v.w < T0);
                    if (h) {
                        int pos = atomicAdd(&S->cnt, h);
                        unsigned base = 4u * (unsigned)i;
                        if (v.x < T0 && pos < CAP)
                            S->cand[pos++] = (((unsigned long long)__float_as_uint(v.x)) << 32) | (base + 0u);
                        if (v.y < T0 && pos < CAP)
                            S->cand[pos++] = (((unsigned long long)__float_as_uint(v.y)) << 32) | (base + 1u);
                        if (v.z < T0 && pos < CAP)
                            S->cand[pos++] = (((unsigned long long)__float_as_uint(v.z)) << 32) | (base + 2u);
                        if (v.w < T0 && pos < CAP)
                            S->cand[pos++] = (((unsigned long long)__float_as_uint(v.w)) << 32) | (base + 3u);
                    }
                }
            }
        }
        __syncthreads();                  // buffer p fully consumed; cnt final
        int cc = S->cnt;

        // re-arm buffer p for row r + 2*GRID BEFORE the tail (overlap)
        if (tid == 0) {
            int r2 = r + 2 * GRID;
            if (r2 < N_ATOMS)
                arm_row(dm, S->buf[p], smem_u32(&S->mbar[p]), r2);
        }

        // ---- exact fallback (rare): rescan this row from GLOBAL ----
        if (cc < KNBR || cc > CAP) {
            const float4* g4 = reinterpret_cast<const float4*>(dm + (size_t)r * ROW_F);
            float t = T0;
            while (cc < KNBR || cc > CAP) {
                t = (cc < KNBR) ? t * 8.0f : t * 0.25f;
                __syncthreads();
                if (tid == 0) S->cnt = 0;
                __syncthreads();
                for (int i = tid; i < ROW_F / 4; i += THREADS) {
                    float4 v = __ldg(g4 + i);
                    if (fminf(fminf(v.x, v.y), fminf(v.z, v.w)) < t) {
                        int h = (v.x < t) + (v.y < t) + (v.z < t) + (v.w < t);
                        int pos = atomicAdd(&S->cnt, h);
                        unsigned base = 4u * (unsigned)i;
                        if (v.x < t && pos < CAP)
                            S->cand[pos++] = (((unsigned long long)__float_as_uint(v.x)) << 32) | (base + 0u);
                        if (v.y < t && pos < CAP)
                            S->cand[pos++] = (((unsigned long long)__float_as_uint(v.y)) << 32) | (base + 1u);
                        if (v.z < t && pos < CAP)
                            S->cand[pos++] = (((unsigned long long)__float_as_uint(v.z)) << 32) | (base + 2u);
                        if (v.w < t && pos < CAP)
                            S->cand[pos++] = (((unsigned long long)__float_as_uint(v.w)) << 32) | (base + 3u);
                    }
                }
                __syncthreads();
                cc = S->cnt;
                __syncthreads();
            }
        }

        // ---- parallel rank selection (keys unique -> ranks distinct) ----
        if (tid < cc) {
            unsigned long long mine = S->cand[tid];
            int rank = 0;
            int j = 0;
            for (; j + 4 <= cc; j += 4) {
                rank += (S->cand[j + 0] < mine);
                rank += (S->cand[j + 1] < mine);
                rank += (S->cand[j + 2] < mine);
                rank += (S->cand[j + 3] < mine);
            }
            for (; j < cc; j++) rank += (S->cand[j] < mine);
            if (rank < KNBR) {
                S->d[rank]   = __uint_as_float((unsigned)(mine >> 32));
                S->idx[rank] = (int)(mine & 0xffffffffu);
            }
        }
        __syncthreads();                  // s_d/s_i ready; cand reads done
        if (tid == 0) S->cnt = 0;

        // ---- features: geometric recurrence (2 MUFU per edge) ----
        if (tid < KNBR) {
            float d  = S->d[tid];
            float e0 = __expf(-12.5f * d * d);
            float g  = __expf((25.0f / 49.0f) * d);
            float pw = e0;
            #pragma unroll
            for (int j = 0; j < NBINS; j++) {
                S->feat[tid * NBINS + j] = pw * S->tc[j];
                pw *= g;
            }
            size_t eo = (size_t)r * (2 * KNBR) + 2 * tid;
            out[eo]     = (float)r;
            out[eo + 1] = (float)S->idx[tid];
        }
        __syncthreads();

        // ---- coalesced feature writeback ----
        float* __restrict__ outF = out + (size_t)N_ATOMS * KNBR * 2
                                       + (size_t)r * (KNBR * NBINS);
        #pragma unroll
        for (int i = tid; i < KNBR * NBINS; i += THREADS)
            outF[i] = S->feat[i];
        // cnt reset + feat reads complete before next row's atomics/waits:
        // ordering provided by the __syncthreads above and the mbar acquire.
    }
}

extern "C" void kernel_launch(void* const* d_in, const int* in_sizes, int n_in,
                              void* d_out, int out_size)
{
    (void)in_sizes; (void)n_in; (void)out_size;
    const float* dm = (const float*)d_in[0];
    float* out = (float*)d_out;
    cudaFuncSetAttribute(edge_featurizer_kernel,
                         cudaFuncAttributeMaxDynamicSharedMemorySize,
                         (int)sizeof(Smem));
    edge_featurizer_kernel<<<GRID, THREADS, sizeof(Smem)>>>(dm, out);
}

// round 9
// speedup vs baseline: 1.3884x; 1.2083x over previous
#include <cuda_runtime.h>
#include <stdint.h>

// EdgeFeaturizer R9: R5 pipeline (4x8KB cp.async.bulk chunked staging, occ 6)
// + parallel stage-free tail (direct expf per (edge,bin), no s_feat, 2 barriers).

#define N_ATOMS   8192
#define KNBR      12
#define NBINS     50
#define CAP       192
#define THREADS   256
#define T0        0.0035f
#define CHUNKS    4
#define CHUNK_F   2048          // floats per chunk (8 KB)
#define CHUNK_V   512           // float4 per chunk

__device__ __forceinline__ unsigned smem_u32(const void* p) {
    return (unsigned)__cvta_generic_to_shared(p);
}

__device__ __forceinline__ void mbar_wait0(unsigned mb) {
    unsigned done;
    asm volatile(
        "{\n\t.reg .pred p;\n\t"
        "mbarrier.try_wait.parity.acquire.cta.shared::cta.b64 p, [%1], 0;\n\t"
        "selp.b32 %0, 1, 0, p;\n\t}"
        : "=r"(done) : "r"(mb) : "memory");
    if (!done) {
        asm volatile(
            "{\n\t.reg .pred P1;\n\t"
            "WL_%=:\n\t"
            "mbarrier.try_wait.parity.acquire.cta.shared::cta.b64 P1, [%0], 0, 0x989680;\n\t"
            "@P1 bra.uni WD_%=;\n\t"
            "bra.uni WL_%=;\n\t"
            "WD_%=:\n\t}"
            :: "r"(mb) : "memory");
    }
}

__global__ __launch_bounds__(THREADS, 6)
void edge_featurizer_kernel(const float* __restrict__ dm, float* __restrict__ out)
{
    __shared__ __align__(128) float s_row[N_ATOMS];     // 32 KB row stage
    __shared__ unsigned long long cand[CAP];
    __shared__ int   s_cnt;
    __shared__ float s_d[KNBR];
    __shared__ int   s_i[KNBR];
    __shared__ __align__(8) unsigned long long s_mbar[CHUNKS];

    const int tid = threadIdx.x;
    const int row = blockIdx.x;

    if (tid == 0) {
        s_cnt = 0;
        #pragma unroll
        for (int c = 0; c < CHUNKS; c++)
            asm volatile("mbarrier.init.shared.b64 [%0], 1;"
                         :: "r"(smem_u32(&s_mbar[c])) : "memory");
    }
    __syncthreads();

    // ---- issue all 4 bulk copies up front (TMA path, zero LDG pressure) ----
    if (tid == 0) {
        const char* src = (const char*)(dm + (size_t)row * N_ATOMS);
        #pragma unroll
        for (int c = 0; c < CHUNKS; c++) {
            unsigned mb  = smem_u32(&s_mbar[c]);
            unsigned dst = smem_u32(&s_row[c * CHUNK_F]);
            asm volatile("mbarrier.arrive.expect_tx.shared.b64 _, [%0], %1;"
                         :: "r"(mb), "r"(CHUNK_F * 4) : "memory");
            asm volatile(
                "cp.async.bulk.shared::cta.global.mbarrier::complete_tx::bytes "
                "[%0], [%1], %2, [%3];"
                :: "r"(dst), "l"(src + (size_t)c * CHUNK_F * 4),
                   "r"(CHUNK_F * 4), "r"(mb) : "memory");
        }
    }

    const float4* s4 = reinterpret_cast<const float4*>(s_row);

    // ---- Phase 1: chunk-pipelined scan from SMEM ----
    #pragma unroll
    for (int c = 0; c < CHUNKS; c++) {
        mbar_wait0(smem_u32(&s_mbar[c]));
        const int i0 = c * CHUNK_V + tid;
        const int i1 = i0 + THREADS;
        float4 v0 = s4[i0];
        float4 v1 = s4[i1];
        float m0 = fminf(fminf(v0.x, v0.y), fminf(v0.z, v0.w));
        float m1 = fminf(fminf(v1.x, v1.y), fminf(v1.z, v1.w));
        if (fminf(m0, m1) < T0) {                     // rare per-thread body
            #pragma unroll
            for (int j = 0; j < 2; j++) {
                float4 v = (j == 0) ? v0 : v1;
                int    i = (j == 0) ? i0 : i1;
                int h = (v.x < T0) + (v.y < T0) + (v.z < T0) + (v.w < T0);
                if (h) {
                    int p = atomicAdd(&s_cnt, h);
                    unsigned base = 4u * (unsigned)i;
                    if (v.x < T0 && p < CAP)
                        cand[p++] = (((unsigned long long)__float_as_uint(v.x)) << 32) | (base + 0u);
                    if (v.y < T0 && p < CAP)
                        cand[p++] = (((unsigned long long)__float_as_uint(v.y)) << 32) | (base + 1u);
                    if (v.z < T0 && p < CAP)
                        cand[p++] = (((unsigned long long)__float_as_uint(v.z)) << 32) | (base + 2u);
                    if (v.w < T0 && p < CAP)
                        cand[p++] = (((unsigned long long)__float_as_uint(v.w)) << 32) | (base + 3u);
                }
            }
        }
    }
    __syncthreads();

    // ---- exact fallback: rescan from SMEM with adjusted t (rare) ----
    int c = s_cnt;
    float t = T0;
    while (c < KNBR || c > CAP) {
        t = (c < KNBR) ? t * 8.0f : t * 0.25f;
        __syncthreads();
        if (tid == 0) s_cnt = 0;
        __syncthreads();
        #pragma unroll
        for (int ii = 0; ii < N_ATOMS / 4 / THREADS; ii++) {
            int i = tid + ii * THREADS;
            float4 v = s4[i];
            if (fminf(fminf(v.x, v.y), fminf(v.z, v.w)) < t) {
                int h = (v.x < t) + (v.y < t) + (v.z < t) + (v.w < t);
                int p = atomicAdd(&s_cnt, h);
                unsigned base = 4u * (unsigned)i;
                if (v.x < t && p < CAP)
                    cand[p++] = (((unsigned long long)__float_as_uint(v.x)) << 32) | (base + 0u);
                if (v.y < t && p < CAP)
                    cand[p++] = (((unsigned long long)__float_as_uint(v.y)) << 32) | (base + 1u);
                if (v.z < t && p < CAP)
                    cand[p++] = (((unsigned long long)__float_as_uint(v.z)) << 32) | (base + 2u);
                if (v.w < t && p < CAP)
                    cand[p++] = (((unsigned long long)__float_as_uint(v.w)) << 32) | (base + 3u);
            }
        }
        __syncthreads();
        c = s_cnt;
        __syncthreads();
    }

    // ---- Phase 2: parallel rank selection (keys unique -> ranks distinct) ----
    if (tid < c) {
        unsigned long long mine = cand[tid];
        int rank = 0;
        int j = 0;
        for (; j + 4 <= c; j += 4) {
            rank += (cand[j + 0] < mine);
            rank += (cand[j + 1] < mine);
            rank += (cand[j + 2] < mine);
            rank += (cand[j + 3] < mine);
        }
        for (; j < c; j++) rank += (cand[j] < mine);
        if (rank < KNBR) {
            s_d[rank] = __uint_as_float((unsigned)(mine >> 32));
            s_i[rank] = (int)(mine & 0xffffffffu);
        }
    }
    __syncthreads();

    // ---- Phase 3: fully parallel output (no staging, direct expf) ----
    if (tid < KNBR) {
        size_t eo = (size_t)row * (2 * KNBR) + 2 * tid;
        out[eo]     = (float)row;
        out[eo + 1] = (float)s_i[tid];
    }
    float* __restrict__ outF = out + (size_t)N_ATOMS * KNBR * 2
                                   + (size_t)row * (KNBR * NBINS);
    #pragma unroll
    for (int i = tid; i < KNBR * NBINS; i += THREADS) {
        int e = i / NBINS;
        int j = i - e * NBINS;
        float z = (s_d[e] - (float)j * (1.0f / 49.0f)) * 5.0f;   // /WIDTH=0.2
        outF[i] = __expf(-0.5f * z * z);
    }
}

extern "C" void kernel_launch(void* const* d_in, const int* in_sizes, int n_in,
                              void* d_out, int out_size)
{
    (void)in_sizes; (void)n_in; (void)out_size;
    const float* dm = (const float*)d_in[0];
    float* out = (float*)d_out;
    edge_featurizer_kernel<<<N_ATOMS, THREADS>>>(dm, out);
}